// round 14
// baseline (speedup 1.0000x reference)
#include <cuda_runtime.h>

#define B_ 2
#define NA 32768
#define NG 32
#define NC 15
#define PI_F 3.1415926f
#define TPB 256
#define CHA 64                         // anchors per chunk
#define CPB 512                        // chunks per batch (NA/CHA)
#define NCHUNK (B_ * CPB)              // 1024
#define NBLK 296                       // 2 blocks per SM x 148 SMs, all co-resident

// ---------------- persistent scratch ----------------
#define F4 0xFFFFFFFFull,0xFFFFFFFFull,0xFFFFFFFFull,0xFFFFFFFFull
#define F16 F4,F4,F4,F4
__device__ unsigned long long d_gtbest[B_ * NG] = {F16, F16, F16, F16};
__device__ unsigned long long d_abest[B_ * NA];
__device__ double d_sum_cls[B_];
__device__ double d_sum_reg[B_];
__device__ int    d_numpos[B_];
__device__ int    d_workA;
__device__ int    d_workB;
__device__ volatile int d_bar1;
__device__ int    d_bar2;

__device__ __forceinline__ void make_quad(float cx, float cy, float w, float h,
                                          float th_deg, float* qx, float* qy,
                                          float* signed_area) {
    float ang = th_deg * (PI_F / 180.0f);
    float c = cosf(ang), s = sinf(ang);
    const float ddx[4] = {-0.5f, 0.5f, 0.5f, -0.5f};
    const float ddy[4] = {-0.5f, -0.5f, 0.5f, 0.5f};
#pragma unroll
    for (int k = 0; k < 4; k++) {
        qx[k] = cx + ddx[k] * w * c - ddy[k] * h * s;
        qy[k] = cy + ddx[k] * w * s + ddy[k] * h * c;
    }
    float sa = 0.0f;
#pragma unroll
    for (int k = 0; k < 4; k++) {
        int nk = (k + 1) & 3;
        sa += qx[k] * qy[nk] - qx[nk] * qy[k];
    }
    *signed_area = sa;
}

// ---------------- persistent fused kernel with dynamic chunking ----------------
__global__ void __launch_bounds__(TPB, 4) kFused(
    const float* __restrict__ cls, const float* __restrict__ reg,
    const float* __restrict__ anchors, const float* __restrict__ ann,
    float* __restrict__ out)
{
    // -------- shared --------
    __shared__ float4 g_sq[NG];
    __shared__ float4 g_quad[NG][2];
    __shared__ float4 g_edge[NG][2];
    __shared__ float2 g_misc[NG];
    __shared__ unsigned long long sbest[NG];
    __shared__ unsigned long long sab[CHA];
    __shared__ unsigned short s_pairs[CHA * NG];   // 4KB
    __shared__ int s_np, s_chunk;
    __shared__ float swx[8][TPB], swy[8][TPB];
    __shared__ float s_aqx[4][CHA], s_aqy[4][CHA], s_aarea[CHA];
    __shared__ float s_acx[CHA], s_acy[CHA], s_ssa[CHA], s_asq[CHA];
    __shared__ float s_aw[CHA], s_ah[CHA], s_ath[CHA];
    __shared__ unsigned char s_isforced[CHA];
    __shared__ double swc[TPB / 32], swr[TPB / 32];
    __shared__ int    swp_[TPB / 32];

    int t = threadIdx.x;
    int w = t >> 5, lane = t & 31;
    int bprev = -1;

    // ================= PHASE A: dynamic chunks =================
    for (;;) {
        if (t == 0) s_chunk = atomicAdd(&d_workA, 1);
        __syncthreads();
        int c = s_chunk;
        if (c >= NCHUNK) break;
        int b = c >> 9;                // CPB = 512
        int a0 = (c & (CPB - 1)) << 6; // *CHA
        bool newb = (b != bprev);
        bprev = b;

        // ---- per-chunk setup ----
        if (t < CHA) {
            int ai = t, i = a0 + ai;
            const float* ab = anchors + ((size_t)b * NA + i) * 5;
            float x0 = ab[0], y0 = ab[1], x1 = ab[2], y1 = ab[3], ath = ab[4];
            float acx = (x0 + x1) * 0.5f, acy = (y0 + y1) * 0.5f;
            float aw = x1 - x0, ah = y1 - y0;
            float aqx[4], aqy[4], sa_a;
            make_quad(acx, acy, aw, ah, ath, aqx, aqy, &sa_a);
            bool arev = (sa_a < 0.0f);
#pragma unroll
            for (int k = 0; k < 4; k++) {
                int src = arev ? (3 - k) : k;
                s_aqx[k][ai] = aqx[src];
                s_aqy[k][ai] = aqy[src];
            }
            s_aarea[ai] = 0.5f * fabsf(sa_a);
            s_acx[ai] = acx; s_acy[ai] = acy;
            float ssa = fmaxf(aw, ah) * 0.5f;
            s_ssa[ai] = ssa;
            float as0 = acx - ssa, as1 = acy - ssa, as2 = acx + ssa, as3 = acy + ssa;
            s_asq[ai] = (as2 - as0) * (as3 - as1);
            s_aw[ai] = aw; s_ah[ai] = ah; s_ath[ai] = ath;
        } else if (t < CHA + NG) {
            int j = t - CHA;
            sbest[j] = 0ULL;
            if (newb) {
                const float* gb = ann + ((size_t)b * NG + j) * 6;
                float x0 = gb[0], y0 = gb[1], x1 = gb[2], y1 = gb[3], th = gb[4];
                float cx = (x0 + x1) * 0.5f, cy = (y0 + y1) * 0.5f;
                float gw = x1 - x0, gh = y1 - y0;
                float qx[4], qy[4], sa;
                make_quad(cx, cy, gw, gh, th, qx, qy, &sa);
                bool rev = (sa < 0.0f);
                float cqx[4], cqy[4];
#pragma unroll
                for (int k = 0; k < 4; k++) {
                    int src = rev ? (3 - k) : k;
                    cqx[k] = qx[src]; cqy[k] = qy[src];
                }
                g_quad[j][0] = make_float4(cqx[0], cqy[0], cqx[1], cqy[1]);
                g_quad[j][1] = make_float4(cqx[2], cqy[2], cqx[3], cqy[3]);
                g_edge[j][0] = make_float4(cqx[1] - cqx[0], cqy[1] - cqy[0],
                                           cqx[2] - cqx[1], cqy[2] - cqy[1]);
                g_edge[j][1] = make_float4(cqx[3] - cqx[2], cqy[3] - cqy[2],
                                           cqx[0] - cqx[3], cqy[0] - cqy[3]);
                float ss = fmaxf(gw, gh) * 0.5f;
                float s0 = cx - ss, s1 = cy - ss, s2 = cx + ss, s3 = cy + ss;
                g_sq[j] = make_float4(s0, s1, s2, s3);
                g_misc[j] = make_float2(0.5f * fabsf(sa), (s2 - s0) * (s3 - s1));
            }
        } else if (t < 2 * CHA + NG) {
            sab[t - CHA - NG] = 0xFFFFFFFFull;   // iou=0, g=0
        }
        if (t == 0) s_np = 0;
        __syncthreads();

        // ---- gate: 4 threads/anchor x 8 GTs ----
        int ai = t & (CHA - 1);
        int h2 = t >> 6;
        int gbase = h2 << 3;
        float acx = s_acx[ai], acy = s_acy[ai];
        float ssa = s_ssa[ai], area_asq = s_asq[ai];
        float as0 = acx - ssa, as1 = acy - ssa, as2 = acx + ssa, as3 = acy + ssa;

        unsigned gatemask = 0;
#pragma unroll
        for (int k = 0; k < 8; k++) {
            int g = gbase + k;
            float4 v01 = g_quad[g][0];
            float4 v23 = g_quad[g][1];
            float4 e01 = g_edge[g][0];
            float4 e23 = g_edge[g][1];
            float cr0 = e01.x * (acy - v01.y) - e01.y * (acx - v01.x);
            float cr1 = e01.z * (acy - v01.w) - e01.w * (acx - v01.z);
            float cr2 = e23.x * (acy - v23.y) - e23.y * (acx - v23.x);
            float cr3 = e23.z * (acy - v23.w) - e23.w * (acx - v23.z);
            bool allp = (cr0 >= 0.0f) & (cr1 >= 0.0f) & (cr2 >= 0.0f) & (cr3 >= 0.0f);
            bool alln = (cr0 <= 0.0f) & (cr1 <= 0.0f) & (cr2 <= 0.0f) & (cr3 <= 0.0f);
            bool inside = allp | alln;
            float4 sq = g_sq[g];
            float lx = fmaxf(as0, sq.x), ly = fmaxf(as1, sq.y);
            float rx = fminf(as2, sq.z), ry = fminf(as3, sq.w);
            float iw = fmaxf(rx - lx, 0.0f), ih = fmaxf(ry - ly, 0.0f);
            float inter = iw * ih;
            float denom = area_asq + g_misc[g].y - inter + 1e-6f;
            if (inside & (inter > 0.1f * denom)) gatemask |= (1u << k);
        }

        // ---- emit pairs (warp-aggregated) ----
        {
            int cnt = __popc(gatemask);
            int acc = cnt;
#pragma unroll
            for (int off = 1; off < 32; off <<= 1) {
                int v = __shfl_up_sync(0xFFFFFFFFu, acc, off);
                if (lane >= off) acc += v;
            }
            int excl = acc - cnt;
            int total = __shfl_sync(0xFFFFFFFFu, acc, 31);
            int base = 0;
            if (lane == 31 && total > 0) base = atomicAdd(&s_np, total);
            base = __shfl_sync(0xFFFFFFFFu, base, 31);
            int p2 = base + excl;
            unsigned m = gatemask;
            while (m) {
                int k = __ffs(m) - 1;
                m &= m - 1;
                s_pairs[p2++] = (unsigned short)((ai << 5) | (gbase + k));
            }
        }
        __syncthreads();

        // ---- cooperative clip ----
        int np = s_np;
        for (int idx = t; idx < np; idx += TPB) {
            unsigned e = s_pairs[idx];
            int a = e >> 5;
            int g = e & 31;

            float curx[8], cury[8];
#pragma unroll
            for (int k = 0; k < 4; k++) { curx[k] = s_aqx[k][a]; cury[k] = s_aqy[k][a]; }
#pragma unroll
            for (int k = 4; k < 8; k++) { curx[k] = 0.0f; cury[k] = 0.0f; }
            float oa = s_aarea[a];

            float4 v01 = g_quad[g][0];
            float4 v23 = g_quad[g][1];
            float q2x[4] = {v01.x, v01.z, v23.x, v23.z};
            float q2y[4] = {v01.y, v01.w, v23.y, v23.w};

            int n = 4;
#pragma unroll
            for (int ed = 0; ed < 4; ed++) {
                float ax = q2x[ed], ay = q2y[ed];
                float bx = q2x[(ed + 1) & 3], by = q2y[(ed + 1) & 3];
                float dx = bx - ax, dy = by - ay;
                float dcv[8];
#pragma unroll
                for (int ii = 0; ii < 8; ii++)
                    dcv[ii] = dx * (cury[ii] - ay) - dy * (curx[ii] - ax);
                int m2 = 0;
#pragma unroll
                for (int ii = 0; ii < 8; ii++) {
                    if (ii < n) {
                        float dc = dcv[ii];
                        bool nlast = (ii + 1 < n);
                        float qx = nlast ? curx[ii + 1] : curx[0];
                        float qy = nlast ? cury[ii + 1] : cury[0];
                        float dn = nlast ? dcv[ii + 1] : dcv[0];
                        bool kc = (dc >= 0.0f);
                        bool kn = (dn >= 0.0f);
                        if (kc && m2 < 8) { swx[m2][t] = curx[ii]; swy[m2][t] = cury[ii]; m2++; }
                        if ((kc != kn) && m2 < 8) {
                            float den = dc - dn;
                            if (fabsf(den) < 1e-12f) den = 1e-12f;
                            float tt = dc / den;
                            swx[m2][t] = curx[ii] + tt * (qx - curx[ii]);
                            swy[m2][t] = cury[ii] + tt * (qy - cury[ii]);
                            m2++;
                        }
                    }
                }
                n = m2;
                if (n == 0) break;
#pragma unroll
                for (int ii = 0; ii < 8; ii++) { curx[ii] = swx[ii][t]; cury[ii] = swy[ii][t]; }
            }
            float ia = 0.0f;
            if (n >= 3) {
                float s = 0.0f;
#pragma unroll
                for (int ii = 0; ii < 8; ii++) {
                    if (ii < n) {
                        bool nlast = (ii + 1 < n);
                        float nx = nlast ? curx[ii + 1] : curx[0];
                        float ny = nlast ? cury[ii + 1] : cury[0];
                        s += curx[ii] * ny - nx * cury[ii];
                    }
                }
                ia = 0.5f * fabsf(s);
            }
            float iou = ia / (oa + g_misc[g].x - ia + 1e-6f);

            unsigned bits = __float_as_uint(iou);
            atomicMax(&sab[a],
                      ((unsigned long long)bits << 32) |
                      (unsigned long long)(0xFFFFFFFFu - (unsigned)g));
            int oi = a0 + a;   // anchor index within batch
            atomicMax(&sbest[g],
                      ((unsigned long long)bits << 32) |
                      (unsigned long long)(0xFFFFFFFFu - (unsigned)oi));
        }
        __syncthreads();

        if (t < NG && sbest[t] != 0ULL)
            atomicMax(&d_gtbest[b * NG + t], sbest[t]);
        if (t >= CHA && t < 2 * CHA)
            d_abest[(size_t)c * CHA + (t - CHA)] = sab[t - CHA];
        // next iteration's top-of-loop __syncthreads orders reuse of sbest/sab
    }

    // ================= grid barrier (296 blocks, 2/SM, co-resident) =================
    __syncthreads();
    if (t == 0) {
        __threadfence();
        atomicAdd((int*)&d_bar1, 1);
        while (d_bar1 < NBLK) __nanosleep(64);
        __threadfence();
    }
    __syncthreads();

    // ================= LOSS PHASE: dynamic chunks =================
    double c0 = 0.0, c1 = 0.0, r0 = 0.0, r1 = 0.0;
    int p0 = 0, p1 = 0;

    for (;;) {
        if (t == 0) s_chunk = atomicAdd(&d_workB, 1);
        __syncthreads();
        int c = s_chunk;
        if (c >= NCHUNK) break;
        int b = c >> 9;
        int a0 = (c & (CPB - 1)) << 6;

        if (t < CHA) s_isforced[t] = 0;
        __syncthreads();
        if (t < NG) {
            unsigned long long gk = d_gtbest[b * NG + t];
            float mx = __uint_as_float((unsigned)(gk >> 32));
            int fa = (int)(0xFFFFFFFFu - (unsigned)(gk & 0xFFFFFFFFull));
            if (mx < 0.5f) {
                int rel = fa - a0;
                if (rel >= 0 && rel < CHA) s_isforced[rel] = 1;
            }
        }
        __syncthreads();

        int ai = t & (CHA - 1);
        int h2 = t >> 6;
        int i = a0 + ai;
        unsigned long long pk = d_abest[(size_t)c * CHA + ai];
        float im = __uint_as_float((unsigned)(pk >> 32));
        int arg = (int)(0xFFFFFFFFu - (unsigned)(pk & 0xFFFFFFFFull));
        int p = (im >= 0.5f) || (s_isforced[ai] != 0);

        const float* cr = cls + ((size_t)b * NA + i) * NC;
        float csum = 0.0f, rsum = 0.0f;
        int cbeg = h2 << 2;
        int cnum = (h2 == 3) ? 3 : 4;

        if (p) {
            const float* gb = ann + ((size_t)b * NG + arg) * 6;
            int lab = (int)gb[5];
#pragma unroll
            for (int kk = 0; kk < 4; kk++) {
                if (kk < cnum) {
                    int c_ = cbeg + kk;
                    float x = fminf(fmaxf(cr[c_], 1e-4f), 0.9999f);
                    if (c_ == lab) {
                        float om = 1.0f - x;
                        csum += 0.25f * om * om * (-__logf(x + 1e-6f));
                    } else {
                        csum += 0.75f * x * x * (-__logf(1.0f - x + 1e-6f));
                    }
                }
            }
            if (h2 == 0) {
                const float* ab = anchors + ((size_t)b * NA + i) * 5;
                float ax0 = ab[0], ay0 = ab[1], ax1 = ab[2], ay1 = ab[3], ath = ab[4];
                float acx = (ax0 + ax1) * 0.5f, acy = (ay0 + ay1) * 0.5f;
                float aw = ax1 - ax0, ah = ay1 - ay0;
                float gx0 = gb[0], gy0 = gb[1], gx1 = gb[2], gy1 = gb[3], gth = gb[4];
                float gcx = (gx0 + gx1) * 0.5f, gcy = (gy0 + gy1) * 0.5f;
                float gw = gx1 - gx0, gh2f = gy1 - gy0;
                float tgt5[5];
                tgt5[0] = (gcx - acx) / aw;
                tgt5[1] = (gcy - acy) / ah;
                tgt5[2] = logf(gw / aw);
                tgt5[3] = logf(gh2f / ah);
                tgt5[4] = (gth - ath) * (PI_F / 180.0f);
                const float* rr = reg + ((size_t)b * NA + i) * 5;
                const float beta = 1.0f / 9.0f;
#pragma unroll
                for (int k = 0; k < 5; k++) {
                    float diff = fabsf(rr[k] - tgt5[k]);
                    rsum += (diff < beta) ? (0.5f * diff * diff / beta) : (diff - 0.5f * beta);
                }
            }
        } else if (im < 0.4f) {
#pragma unroll
            for (int kk = 0; kk < 4; kk++) {
                if (kk < cnum) {
                    int c_ = cbeg + kk;
                    float x = fminf(fmaxf(cr[c_], 1e-4f), 0.9999f);
                    csum += 0.75f * x * x * (-__logf(1.0f - x + 1e-6f));
                }
            }
        }

        int pc = (h2 == 0) ? p : 0;
        if (b == 0) { c0 += (double)csum; r0 += (double)rsum; p0 += pc; }
        else        { c1 += (double)csum; r1 += (double)rsum; p1 += pc; }
        // top-of-loop __syncthreads orders s_isforced reuse
    }

    // ---- block reduction of 6 accumulators ----
    __syncthreads();
#pragma unroll
    for (int off = 16; off > 0; off >>= 1) {
        c0 += __shfl_down_sync(0xFFFFFFFFu, c0, off);
        c1 += __shfl_down_sync(0xFFFFFFFFu, c1, off);
        r0 += __shfl_down_sync(0xFFFFFFFFu, r0, off);
        r1 += __shfl_down_sync(0xFFFFFFFFu, r1, off);
        p0 += __shfl_down_sync(0xFFFFFFFFu, p0, off);
        p1 += __shfl_down_sync(0xFFFFFFFFu, p1, off);
    }
    if (lane == 0) { swc[w] = c0; swr[w] = r0; swp_[w] = p0; }
    __syncthreads();
    if (t == 0) {
        double tc = 0.0, tr = 0.0; int tp = 0;
#pragma unroll
        for (int k = 0; k < TPB / 32; k++) { tc += swc[k]; tr += swr[k]; tp += swp_[k]; }
        atomicAdd(&d_sum_cls[0], tc);
        atomicAdd(&d_sum_reg[0], tr);
        atomicAdd(&d_numpos[0], tp);
    }
    __syncthreads();
    if (lane == 0) { swc[w] = c1; swr[w] = r1; swp_[w] = p1; }
    __syncthreads();
    if (t == 0) {
        double tc = 0.0, tr = 0.0; int tp = 0;
#pragma unroll
        for (int k = 0; k < TPB / 32; k++) { tc += swc[k]; tr += swr[k]; tp += swp_[k]; }
        atomicAdd(&d_sum_cls[1], tc);
        atomicAdd(&d_sum_reg[1], tr);
        atomicAdd(&d_numpos[1], tp);
        __threadfence();
        int old = atomicAdd(&d_bar2, 1);
        if (old == NBLK - 1) {
            float lc = 0.0f, lr = 0.0f;
            for (int bb = 0; bb < B_; bb++) {
                int npv = d_numpos[bb];
                float npf = (float)(npv > 1 ? npv : 1);
                lc += (float)d_sum_cls[bb] / npf;
                lr += (npv > 0) ? ((float)d_sum_reg[bb] / (npf * 5.0f)) : 0.0f;
            }
            out[0] = 5.0f * (lc / (float)B_);
            out[1] = 2.0f * (lr / (float)B_);
            // reset for next graph replay
            for (int bb = 0; bb < B_; bb++) {
                d_sum_cls[bb] = 0.0;
                d_sum_reg[bb] = 0.0;
                d_numpos[bb] = 0;
            }
            for (int k = 0; k < B_ * NG; k++) d_gtbest[k] = 0xFFFFFFFFull;
            d_workA = 0;
            d_workB = 0;
            d_bar1 = 0;
            __threadfence();
            d_bar2 = 0;
        }
    }
}

// ---------------- launch ----------------
extern "C" void kernel_launch(void* const* d_in, const int* in_sizes, int n_in,
                              void* d_out, int out_size) {
    const float* cls     = (const float*)d_in[0];
    const float* reg     = (const float*)d_in[1];
    const float* anchors = (const float*)d_in[2];
    const float* ann     = (const float*)d_in[3];
    float* out = (float*)d_out;

    kFused<<<NBLK, TPB>>>(cls, reg, anchors, ann, out);
}

// round 15
// speedup vs baseline: 1.7113x; 1.7113x over previous
#include <cuda_runtime.h>

#define B_ 2
#define NA 32768
#define NG 32
#define NC 15
#define PI_F 3.1415926f
#define TPB 256
#define APB 128                       // anchors per block, 2 threads per anchor
#define NBLKX (NA / APB)
#define TOTBLK (NBLKX * B_)

// ---------------- persistent scratch ----------------
#define F4 0xFFFFFFFFull,0xFFFFFFFFull,0xFFFFFFFFull,0xFFFFFFFFull
#define F16 F4,F4,F4,F4
__device__ unsigned long long d_gtbest[B_ * NG] = {F16, F16, F16, F16};
__device__ double d_sum_cls[B_];
__device__ double d_sum_reg[B_];
__device__ int    d_numpos[B_];
__device__ volatile int d_bar1;
__device__ int d_bar2;

__device__ __forceinline__ void make_quad(float cx, float cy, float w, float h,
                                          float th_deg, float* qx, float* qy,
                                          float* signed_area) {
    float ang = th_deg * (PI_F / 180.0f);
    float c = cosf(ang), s = sinf(ang);
    const float ddx[4] = {-0.5f, 0.5f, 0.5f, -0.5f};
    const float ddy[4] = {-0.5f, -0.5f, 0.5f, 0.5f};
#pragma unroll
    for (int k = 0; k < 4; k++) {
        qx[k] = cx + ddx[k] * w * c - ddy[k] * h * s;
        qy[k] = cy + ddx[k] * w * s + ddy[k] * h * c;
    }
    float sa = 0.0f;
#pragma unroll
    for (int k = 0; k < 4; k++) {
        int nk = (k + 1) & 3;
        sa += qx[k] * qy[nk] - qx[nk] * qy[k];
    }
    *signed_area = sa;
}

// ---------------- fused kernel: 2 threads per anchor, grid barrier ----------------
__global__ void __launch_bounds__(TPB, 4) kFused(
    const float* __restrict__ cls, const float* __restrict__ reg,
    const float* __restrict__ anchors, const float* __restrict__ ann,
    float* __restrict__ out)
{
    // -------- shared --------
    __shared__ float4 g_sq[NG];
    __shared__ float4 g_quad[NG][2];                // CCW verts
    __shared__ float4 g_edge[NG][2];                // hoisted CCW edge vectors
    __shared__ float2 g_misc[NG];                   // (gt quad area, gt square area)
    __shared__ unsigned long long sbest[NG];
    __shared__ unsigned long long sab[APB];
    __shared__ unsigned short s_pairs[APB * NG];
    __shared__ int s_np;
    __shared__ float swx[8][TPB], swy[8][TPB];      // clip write scratch
    __shared__ float s_aqx[4][APB], s_aqy[4][APB], s_aarea[APB];
    __shared__ float s_acx[APB], s_acy[APB], s_ssa[APB], s_asq[APB];
    __shared__ float s_aw[APB], s_ah[APB], s_ath[APB];
    __shared__ double swc[TPB / 32], swr[TPB / 32];
    __shared__ int    swp_[TPB / 32];
    __shared__ int    sforce[NG];

    int b = blockIdx.y;
    int t = threadIdx.x;
    int w = t >> 5, lane = t & 31;
    int h = t >> 7;            // half: 0 -> GTs 0..15 & classes 0..7 ; 1 -> GTs 16..31 & classes 8..14
    int ai = t & (APB - 1);
    int i = blockIdx.x * APB + ai;

    if (t == 0) s_np = 0;

    // -------- setup: half0 = anchor geometry, half1 = GT tables + sab init --------
    if (t < APB) {
        const float* ab = anchors + ((size_t)b * NA + i) * 5;
        float x0 = ab[0], y0 = ab[1], x1 = ab[2], y1 = ab[3], ath = ab[4];
        float acx = (x0 + x1) * 0.5f, acy = (y0 + y1) * 0.5f;
        float aw = x1 - x0, ah = y1 - y0;
        float aqx[4], aqy[4], sa_a;
        make_quad(acx, acy, aw, ah, ath, aqx, aqy, &sa_a);
        bool arev = (sa_a < 0.0f);
#pragma unroll
        for (int k = 0; k < 4; k++) {
            int src = arev ? (3 - k) : k;
            s_aqx[k][ai] = aqx[src];
            s_aqy[k][ai] = aqy[src];
        }
        s_aarea[ai] = 0.5f * fabsf(sa_a);
        s_acx[ai] = acx; s_acy[ai] = acy;
        float ssa = fmaxf(aw, ah) * 0.5f;
        s_ssa[ai] = ssa;
        float as0 = acx - ssa, as1 = acy - ssa, as2 = acx + ssa, as3 = acy + ssa;
        s_asq[ai] = (as2 - as0) * (as3 - as1);
        s_aw[ai] = aw; s_ah[ai] = ah; s_ath[ai] = ath;
    } else {
        int j = t - APB;
        sab[j] = 0xFFFFFFFFull;  // iou=0, g=0
        if (j < NG) {
            const float* gb = ann + ((size_t)b * NG + j) * 6;
            float x0 = gb[0], y0 = gb[1], x1 = gb[2], y1 = gb[3], th = gb[4];
            float cx = (x0 + x1) * 0.5f, cy = (y0 + y1) * 0.5f;
            float gw = x1 - x0, gh = y1 - y0;
            float qx[4], qy[4], sa;
            make_quad(cx, cy, gw, gh, th, qx, qy, &sa);
            bool rev = (sa < 0.0f);
            float cqx[4], cqy[4];
#pragma unroll
            for (int k = 0; k < 4; k++) {
                int src = rev ? (3 - k) : k;
                cqx[k] = qx[src]; cqy[k] = qy[src];
            }
            g_quad[j][0] = make_float4(cqx[0], cqy[0], cqx[1], cqy[1]);
            g_quad[j][1] = make_float4(cqx[2], cqy[2], cqx[3], cqy[3]);
            // hoisted edge vectors (bit-identical to the per-anchor subtraction)
            g_edge[j][0] = make_float4(cqx[1] - cqx[0], cqy[1] - cqy[0],
                                       cqx[2] - cqx[1], cqy[2] - cqy[1]);
            g_edge[j][1] = make_float4(cqx[3] - cqx[2], cqy[3] - cqy[2],
                                       cqx[0] - cqx[3], cqy[0] - cqy[3]);
            float ss = fmaxf(gw, gh) * 0.5f;
            float s0 = cx - ss, s1 = cy - ss, s2 = cx + ss, s3 = cy + ss;
            g_sq[j] = make_float4(s0, s1, s2, s3);
            g_misc[j] = make_float2(0.5f * fabsf(sa), (s2 - s0) * (s3 - s1));
            sbest[j] = 0ULL;
        }
    }
    __syncthreads();

    // -------- gate: 16 GTs per thread (division-free, hoisted edges) --------
    float acx = s_acx[ai], acy = s_acy[ai];
    float ssa = s_ssa[ai], area_asq = s_asq[ai];
    float as0 = acx - ssa, as1 = acy - ssa, as2 = acx + ssa, as3 = acy + ssa;

    unsigned gatemask = 0;   // bit k -> GT (h*16 + k)
    int gbase = h << 4;
#pragma unroll 4
    for (int k = 0; k < 16; k++) {
        int g = gbase + k;
        float4 sq = g_sq[g];
        float lx = fmaxf(as0, sq.x), ly = fmaxf(as1, sq.y);
        float rx = fminf(as2, sq.z), ry = fminf(as3, sq.w);
        float iw = fmaxf(rx - lx, 0.0f), ih = fmaxf(ry - ly, 0.0f);
        float inter = iw * ih;
        float denom = area_asq + g_misc[g].y - inter + 1e-6f;

        float4 v01 = g_quad[g][0];
        float4 v23 = g_quad[g][1];
        float4 e01 = g_edge[g][0];
        float4 e23 = g_edge[g][1];
        float cr0 = e01.x * (acy - v01.y) - e01.y * (acx - v01.x);
        float cr1 = e01.z * (acy - v01.w) - e01.w * (acx - v01.z);
        float cr2 = e23.x * (acy - v23.y) - e23.y * (acx - v23.x);
        float cr3 = e23.z * (acy - v23.w) - e23.w * (acx - v23.z);
        bool allp = (cr0 >= 0.0f) && (cr1 >= 0.0f) && (cr2 >= 0.0f) && (cr3 >= 0.0f);
        bool alln = (cr0 <= 0.0f) && (cr1 <= 0.0f) && (cr2 <= 0.0f) && (cr3 <= 0.0f);
        if ((allp || alln) && (inter > 0.1f * denom)) gatemask |= (1u << k);
    }

    // -------- emit pairs (warp-aggregated) --------
    {
        int cnt = __popc(gatemask);
        int acc = cnt;
#pragma unroll
        for (int off = 1; off < 32; off <<= 1) {
            int v = __shfl_up_sync(0xFFFFFFFFu, acc, off);
            if (lane >= off) acc += v;
        }
        int excl = acc - cnt;
        int total = __shfl_sync(0xFFFFFFFFu, acc, 31);
        int base = 0;
        if (lane == 31 && total > 0) base = atomicAdd(&s_np, total);
        base = __shfl_sync(0xFFFFFFFFu, base, 31);
        int p2 = base + excl;
        unsigned m = gatemask;
        while (m) {
            int k = __ffs(m) - 1;
            m &= m - 1;
            s_pairs[p2++] = (unsigned short)((ai << 5) | (gbase + k));
        }
    }
    __syncthreads();

    // -------- cooperative clip --------
    int np = s_np;
    for (int idx = t; idx < np; idx += TPB) {
        unsigned e = s_pairs[idx];
        int a = e >> 5;
        int g = e & 31;

        float curx[8], cury[8];
#pragma unroll
        for (int k = 0; k < 4; k++) { curx[k] = s_aqx[k][a]; cury[k] = s_aqy[k][a]; }
#pragma unroll
        for (int k = 4; k < 8; k++) { curx[k] = 0.0f; cury[k] = 0.0f; }
        float oa = s_aarea[a];

        float4 v01 = g_quad[g][0];
        float4 v23 = g_quad[g][1];
        float q2x[4] = {v01.x, v01.z, v23.x, v23.z};
        float q2y[4] = {v01.y, v01.w, v23.y, v23.w};

        int n = 4;
#pragma unroll
        for (int ed = 0; ed < 4; ed++) {
            float ax = q2x[ed], ay = q2y[ed];
            float bx = q2x[(ed + 1) & 3], by = q2y[(ed + 1) & 3];
            float dx = bx - ax, dy = by - ay;
            float dcv[8];
#pragma unroll
            for (int ii = 0; ii < 8; ii++)
                dcv[ii] = dx * (cury[ii] - ay) - dy * (curx[ii] - ax);
            int m2 = 0;
#pragma unroll
            for (int ii = 0; ii < 8; ii++) {
                if (ii < n) {
                    float dc = dcv[ii];
                    bool nlast = (ii + 1 < n);
                    float qx = nlast ? curx[ii + 1] : curx[0];
                    float qy = nlast ? cury[ii + 1] : cury[0];
                    float dn = nlast ? dcv[ii + 1] : dcv[0];
                    bool kc = (dc >= 0.0f);
                    bool kn = (dn >= 0.0f);
                    if (kc && m2 < 8) { swx[m2][t] = curx[ii]; swy[m2][t] = cury[ii]; m2++; }
                    if ((kc != kn) && m2 < 8) {
                        float den = dc - dn;
                        if (fabsf(den) < 1e-12f) den = 1e-12f;
                        float tt = dc / den;
                        swx[m2][t] = curx[ii] + tt * (qx - curx[ii]);
                        swy[m2][t] = cury[ii] + tt * (qy - cury[ii]);
                        m2++;
                    }
                }
            }
            n = m2;
            if (n == 0) break;
#pragma unroll
            for (int ii = 0; ii < 8; ii++) { curx[ii] = swx[ii][t]; cury[ii] = swy[ii][t]; }
        }
        float ia = 0.0f;
        if (n >= 3) {
            float s = 0.0f;
#pragma unroll
            for (int ii = 0; ii < 8; ii++) {
                if (ii < n) {
                    bool nlast = (ii + 1 < n);
                    float nx = nlast ? curx[ii + 1] : curx[0];
                    float ny = nlast ? cury[ii + 1] : cury[0];
                    s += curx[ii] * ny - nx * cury[ii];
                }
            }
            ia = 0.5f * fabsf(s);
        }
        float iou = ia / (oa + g_misc[g].x - ia + 1e-6f);

        unsigned bits = __float_as_uint(iou);
        atomicMax(&sab[a],
                  ((unsigned long long)bits << 32) |
                  (unsigned long long)(0xFFFFFFFFu - (unsigned)g));
        int oi = blockIdx.x * APB + a;
        atomicMax(&sbest[g],
                  ((unsigned long long)bits << 32) |
                  (unsigned long long)(0xFFFFFFFFu - (unsigned)oi));
    }

    __syncthreads();
    if (t < NG && sbest[t] != 0ULL)
        atomicMax(&d_gtbest[b * NG + t], sbest[t]);

    // -------- grid barrier (512 blocks co-resident) --------
    __syncthreads();
    if (t == 0) {
        __threadfence();
        atomicAdd((int*)&d_bar1, 1);
        while (d_bar1 < TOTBLK) __nanosleep(64);
        __threadfence();
    }
    __syncthreads();

    // -------- loss phase --------
    if (t < NG) {
        unsigned long long pk = d_gtbest[b * NG + t];
        float mx = __uint_as_float((unsigned)(pk >> 32));
        int arg = (int)(0xFFFFFFFFu - (unsigned)(pk & 0xFFFFFFFFull));
        sforce[t] = (mx < 0.5f) ? arg : -1;
    }
    __syncthreads();

    unsigned long long pk = sab[ai];
    float im = __uint_as_float((unsigned)(pk >> 32));
    int arg = (int)(0xFFFFFFFFu - (unsigned)(pk & 0xFFFFFFFFull));
    bool forced = false;
#pragma unroll
    for (int g = 0; g < NG; g++) forced = forced || (sforce[g] == i);
    int p = (im >= 0.5f) || forced;

    const float* cr = cls + ((size_t)b * NA + i) * NC;
    float csum = 0.0f;
    float rsum = 0.0f;

    if (p) {
        const float* gb = ann + ((size_t)b * NG + arg) * 6;
        int lab = (int)gb[5];
        if (h == 0) {
#pragma unroll
            for (int c_ = 0; c_ < 8; c_++) {
                float x = fminf(fmaxf(cr[c_], 1e-4f), 0.9999f);
                if (c_ == lab) {
                    float om = 1.0f - x;
                    csum += 0.25f * om * om * (-__logf(x + 1e-6f));
                } else {
                    csum += 0.75f * x * x * (-__logf(1.0f - x + 1e-6f));
                }
            }
            float gx0 = gb[0], gy0 = gb[1], gx1 = gb[2], gy1 = gb[3], gth = gb[4];
            float gcx = (gx0 + gx1) * 0.5f, gcy = (gy0 + gy1) * 0.5f;
            float gw = gx1 - gx0, gh2 = gy1 - gy0;
            float aw = s_aw[ai], ah = s_ah[ai], ath = s_ath[ai];
            float tgt5[5];
            tgt5[0] = (gcx - acx) / aw;
            tgt5[1] = (gcy - acy) / ah;
            tgt5[2] = logf(gw / aw);
            tgt5[3] = logf(gh2 / ah);
            tgt5[4] = (gth - ath) * (PI_F / 180.0f);
            const float* rr = reg + ((size_t)b * NA + i) * 5;
            const float beta = 1.0f / 9.0f;
#pragma unroll
            for (int k = 0; k < 5; k++) {
                float diff = fabsf(rr[k] - tgt5[k]);
                rsum += (diff < beta) ? (0.5f * diff * diff / beta) : (diff - 0.5f * beta);
            }
        } else {
#pragma unroll
            for (int c_ = 8; c_ < NC; c_++) {
                float x = fminf(fmaxf(cr[c_], 1e-4f), 0.9999f);
                if (c_ == lab) {
                    float om = 1.0f - x;
                    csum += 0.25f * om * om * (-__logf(x + 1e-6f));
                } else {
                    csum += 0.75f * x * x * (-__logf(1.0f - x + 1e-6f));
                }
            }
        }
    } else if (im < 0.4f) {
        if (h == 0) {
#pragma unroll
            for (int c_ = 0; c_ < 8; c_++) {
                float x = fminf(fmaxf(cr[c_], 1e-4f), 0.9999f);
                csum += 0.75f * x * x * (-__logf(1.0f - x + 1e-6f));
            }
        } else {
#pragma unroll
            for (int c_ = 8; c_ < NC; c_++) {
                float x = fminf(fmaxf(cr[c_], 1e-4f), 0.9999f);
                csum += 0.75f * x * x * (-__logf(1.0f - x + 1e-6f));
            }
        }
    }

    // warp reduce (double)
    double dc_ = (double)csum, dr_ = (double)rsum;
    int ip = (h == 0) ? p : 0;
#pragma unroll
    for (int off = 16; off > 0; off >>= 1) {
        dc_ += __shfl_down_sync(0xFFFFFFFFu, dc_, off);
        dr_ += __shfl_down_sync(0xFFFFFFFFu, dr_, off);
        ip  += __shfl_down_sync(0xFFFFFFFFu, ip, off);
    }
    if (lane == 0) { swc[w] = dc_; swr[w] = dr_; swp_[w] = ip; }
    __syncthreads();
    if (t == 0) {
        double tc = 0.0, tr = 0.0;
        int tp = 0;
#pragma unroll
        for (int k = 0; k < TPB / 32; k++) { tc += swc[k]; tr += swr[k]; tp += swp_[k]; }
        atomicAdd(&d_sum_cls[b], tc);
        atomicAdd(&d_sum_reg[b], tr);
        atomicAdd(&d_numpos[b], tp);
        __threadfence();
        int old = atomicAdd(&d_bar2, 1);
        if (old == TOTBLK - 1) {
            float lc = 0.0f, lr = 0.0f;
            for (int bb = 0; bb < B_; bb++) {
                int npv = d_numpos[bb];
                float npf = (float)(npv > 1 ? npv : 1);
                lc += (float)d_sum_cls[bb] / npf;
                lr += (npv > 0) ? ((float)d_sum_reg[bb] / (npf * 5.0f)) : 0.0f;
            }
            out[0] = 5.0f * (lc / (float)B_);
            out[1] = 2.0f * (lr / (float)B_);
            for (int bb = 0; bb < B_; bb++) {
                d_sum_cls[bb] = 0.0;
                d_sum_reg[bb] = 0.0;
                d_numpos[bb] = 0;
            }
            for (int k = 0; k < B_ * NG; k++) d_gtbest[k] = 0xFFFFFFFFull;
            d_bar1 = 0;
            __threadfence();
            d_bar2 = 0;
        }
    }
}

// ---------------- launch ----------------
extern "C" void kernel_launch(void* const* d_in, const int* in_sizes, int n_in,
                              void* d_out, int out_size) {
    const float* cls     = (const float*)d_in[0];
    const float* reg     = (const float*)d_in[1];
    const float* anchors = (const float*)d_in[2];
    const float* ann     = (const float*)d_in[3];
    float* out = (float*)d_out;

    dim3 grid(NBLKX, B_);
    kFused<<<grid, TPB>>>(cls, reg, anchors, ann, out);
}

// round 16
// speedup vs baseline: 1.7650x; 1.0314x over previous
#include <cuda_runtime.h>

#define B_ 2
#define NA 32768
#define NG 32
#define NC 15
#define PI_F 3.1415926f
#define TPB 256
#define APB 128                       // anchors per block, 2 threads per anchor
#define NBLKX (NA / APB)
#define TOTBLK (NBLKX * B_)

// ---------------- persistent scratch ----------------
#define F4 0xFFFFFFFFull,0xFFFFFFFFull,0xFFFFFFFFull,0xFFFFFFFFull
#define F16 F4,F4,F4,F4
__device__ unsigned long long d_gtbest[B_ * NG] = {F16, F16, F16, F16};
__device__ double d_sum_cls[B_];
__device__ double d_sum_reg[B_];
__device__ int    d_numpos[B_];
__device__ volatile int d_bar1;
__device__ int d_bar2;

__device__ __forceinline__ void make_quad(float cx, float cy, float w, float h,
                                          float th_deg, float* qx, float* qy,
                                          float* signed_area) {
    float ang = th_deg * (PI_F / 180.0f);
    float c = cosf(ang), s = sinf(ang);
    const float ddx[4] = {-0.5f, 0.5f, 0.5f, -0.5f};
    const float ddy[4] = {-0.5f, -0.5f, 0.5f, 0.5f};
#pragma unroll
    for (int k = 0; k < 4; k++) {
        qx[k] = cx + ddx[k] * w * c - ddy[k] * h * s;
        qy[k] = cy + ddx[k] * w * s + ddy[k] * h * c;
    }
    float sa = 0.0f;
#pragma unroll
    for (int k = 0; k < 4; k++) {
        int nk = (k + 1) & 3;
        sa += qx[k] * qy[nk] - qx[nk] * qy[k];
    }
    *signed_area = sa;
}

// ---------------- fused kernel: 2 threads per anchor, grid barrier ----------------
__global__ void __launch_bounds__(TPB, 4) kFused(
    const float* __restrict__ cls, const float* __restrict__ reg,
    const float* __restrict__ anchors, const float* __restrict__ ann,
    float* __restrict__ out)
{
    // -------- shared --------
    __shared__ float4 g_sq[NG];
    __shared__ float4 g_quad[NG][2];                // CCW verts
    __shared__ float4 g_edge[NG][2];                // hoisted CCW edge vectors
    __shared__ float2 g_misc[NG];                   // (gt quad area, gt square area)
    __shared__ unsigned long long sbest[NG];
    __shared__ unsigned long long sab[APB];
    __shared__ unsigned short s_pairs[APB * NG];
    __shared__ int s_np;
    __shared__ float swx[8][TPB], swy[8][TPB];      // clip write scratch
    __shared__ float s_aqx[4][APB], s_aqy[4][APB], s_aarea[APB];
    __shared__ float s_acx[APB], s_acy[APB], s_ssa[APB], s_asq[APB];
    __shared__ float s_aw[APB], s_ah[APB], s_ath[APB];
    __shared__ double swc[TPB / 32], swr[TPB / 32];
    __shared__ int    swp_[TPB / 32];
    __shared__ unsigned char s_isforced[APB];

    int b = blockIdx.y;
    int t = threadIdx.x;
    int w = t >> 5, lane = t & 31;
    int h = t >> 7;            // half: 0 -> GTs 0..15 & classes 0..7 ; 1 -> GTs 16..31 & classes 8..14
    int ai = t & (APB - 1);
    int i = blockIdx.x * APB + ai;

    if (t == 0) s_np = 0;

    // -------- setup: half0 = anchor geometry, half1 = GT tables + sab init --------
    if (t < APB) {
        const float* ab = anchors + ((size_t)b * NA + i) * 5;
        float x0 = ab[0], y0 = ab[1], x1 = ab[2], y1 = ab[3], ath = ab[4];
        float acx = (x0 + x1) * 0.5f, acy = (y0 + y1) * 0.5f;
        float aw = x1 - x0, ah = y1 - y0;
        float aqx[4], aqy[4], sa_a;
        make_quad(acx, acy, aw, ah, ath, aqx, aqy, &sa_a);
        bool arev = (sa_a < 0.0f);
#pragma unroll
        for (int k = 0; k < 4; k++) {
            int src = arev ? (3 - k) : k;
            s_aqx[k][ai] = aqx[src];
            s_aqy[k][ai] = aqy[src];
        }
        s_aarea[ai] = 0.5f * fabsf(sa_a);
        s_acx[ai] = acx; s_acy[ai] = acy;
        float ssa = fmaxf(aw, ah) * 0.5f;
        s_ssa[ai] = ssa;
        float as0 = acx - ssa, as1 = acy - ssa, as2 = acx + ssa, as3 = acy + ssa;
        s_asq[ai] = (as2 - as0) * (as3 - as1);
        s_aw[ai] = aw; s_ah[ai] = ah; s_ath[ai] = ath;
        s_isforced[ai] = 0;
    } else {
        int j = t - APB;
        sab[j] = 0xFFFFFFFFull;  // iou=0, g=0
        if (j < NG) {
            const float* gb = ann + ((size_t)b * NG + j) * 6;
            float x0 = gb[0], y0 = gb[1], x1 = gb[2], y1 = gb[3], th = gb[4];
            float cx = (x0 + x1) * 0.5f, cy = (y0 + y1) * 0.5f;
            float gw = x1 - x0, gh = y1 - y0;
            float qx[4], qy[4], sa;
            make_quad(cx, cy, gw, gh, th, qx, qy, &sa);
            bool rev = (sa < 0.0f);
            float cqx[4], cqy[4];
#pragma unroll
            for (int k = 0; k < 4; k++) {
                int src = rev ? (3 - k) : k;
                cqx[k] = qx[src]; cqy[k] = qy[src];
            }
            g_quad[j][0] = make_float4(cqx[0], cqy[0], cqx[1], cqy[1]);
            g_quad[j][1] = make_float4(cqx[2], cqy[2], cqx[3], cqy[3]);
            // hoisted edge vectors (bit-identical to the per-anchor subtraction)
            g_edge[j][0] = make_float4(cqx[1] - cqx[0], cqy[1] - cqy[0],
                                       cqx[2] - cqx[1], cqy[2] - cqy[1]);
            g_edge[j][1] = make_float4(cqx[3] - cqx[2], cqy[3] - cqy[2],
                                       cqx[0] - cqx[3], cqy[0] - cqy[3]);
            float ss = fmaxf(gw, gh) * 0.5f;
            float s0 = cx - ss, s1 = cy - ss, s2 = cx + ss, s3 = cy + ss;
            g_sq[j] = make_float4(s0, s1, s2, s3);
            g_misc[j] = make_float2(0.5f * fabsf(sa), (s2 - s0) * (s3 - s1));
            sbest[j] = 0ULL;
        }
    }
    __syncthreads();

    // -------- gate: 16 GTs per thread (division-free, hoisted edges) --------
    float acx = s_acx[ai], acy = s_acy[ai];
    float ssa = s_ssa[ai], area_asq = s_asq[ai];
    float as0 = acx - ssa, as1 = acy - ssa, as2 = acx + ssa, as3 = acy + ssa;

    unsigned gatemask = 0;   // bit k -> GT (h*16 + k)
    int gbase = h << 4;
#pragma unroll 4
    for (int k = 0; k < 16; k++) {
        int g = gbase + k;
        float4 sq = g_sq[g];
        float lx = fmaxf(as0, sq.x), ly = fmaxf(as1, sq.y);
        float rx = fminf(as2, sq.z), ry = fminf(as3, sq.w);
        float iw = fmaxf(rx - lx, 0.0f), ih = fmaxf(ry - ly, 0.0f);
        float inter = iw * ih;
        float denom = area_asq + g_misc[g].y - inter + 1e-6f;

        float4 v01 = g_quad[g][0];
        float4 v23 = g_quad[g][1];
        float4 e01 = g_edge[g][0];
        float4 e23 = g_edge[g][1];
        float cr0 = e01.x * (acy - v01.y) - e01.y * (acx - v01.x);
        float cr1 = e01.z * (acy - v01.w) - e01.w * (acx - v01.z);
        float cr2 = e23.x * (acy - v23.y) - e23.y * (acx - v23.x);
        float cr3 = e23.z * (acy - v23.w) - e23.w * (acx - v23.z);
        bool allp = (cr0 >= 0.0f) && (cr1 >= 0.0f) && (cr2 >= 0.0f) && (cr3 >= 0.0f);
        bool alln = (cr0 <= 0.0f) && (cr1 <= 0.0f) && (cr2 <= 0.0f) && (cr3 <= 0.0f);
        if ((allp || alln) && (inter > 0.1f * denom)) gatemask |= (1u << k);
    }

    // -------- emit pairs (warp-aggregated) --------
    {
        int cnt = __popc(gatemask);
        int acc = cnt;
#pragma unroll
        for (int off = 1; off < 32; off <<= 1) {
            int v = __shfl_up_sync(0xFFFFFFFFu, acc, off);
            if (lane >= off) acc += v;
        }
        int excl = acc - cnt;
        int total = __shfl_sync(0xFFFFFFFFu, acc, 31);
        int base = 0;
        if (lane == 31 && total > 0) base = atomicAdd(&s_np, total);
        base = __shfl_sync(0xFFFFFFFFu, base, 31);
        int p2 = base + excl;
        unsigned m = gatemask;
        while (m) {
            int k = __ffs(m) - 1;
            m &= m - 1;
            s_pairs[p2++] = (unsigned short)((ai << 5) | (gbase + k));
        }
    }
    __syncthreads();

    // -------- cooperative clip --------
    int np = s_np;
    for (int idx = t; idx < np; idx += TPB) {
        unsigned e = s_pairs[idx];
        int a = e >> 5;
        int g = e & 31;

        float curx[8], cury[8];
#pragma unroll
        for (int k = 0; k < 4; k++) { curx[k] = s_aqx[k][a]; cury[k] = s_aqy[k][a]; }
#pragma unroll
        for (int k = 4; k < 8; k++) { curx[k] = 0.0f; cury[k] = 0.0f; }
        float oa = s_aarea[a];

        float4 v01 = g_quad[g][0];
        float4 v23 = g_quad[g][1];
        float q2x[4] = {v01.x, v01.z, v23.x, v23.z};
        float q2y[4] = {v01.y, v01.w, v23.y, v23.w};

        int n = 4;
#pragma unroll
        for (int ed = 0; ed < 4; ed++) {
            float ax = q2x[ed], ay = q2y[ed];
            float bx = q2x[(ed + 1) & 3], by = q2y[(ed + 1) & 3];
            float dx = bx - ax, dy = by - ay;
            float dcv[8];
#pragma unroll
            for (int ii = 0; ii < 8; ii++)
                dcv[ii] = dx * (cury[ii] - ay) - dy * (curx[ii] - ax);
            int m2 = 0;
#pragma unroll
            for (int ii = 0; ii < 8; ii++) {
                if (ii < n) {
                    float dc = dcv[ii];
                    bool nlast = (ii + 1 < n);
                    float qx = nlast ? curx[ii + 1] : curx[0];
                    float qy = nlast ? cury[ii + 1] : cury[0];
                    float dn = nlast ? dcv[ii + 1] : dcv[0];
                    bool kc = (dc >= 0.0f);
                    bool kn = (dn >= 0.0f);
                    if (kc && m2 < 8) { swx[m2][t] = curx[ii]; swy[m2][t] = cury[ii]; m2++; }
                    if ((kc != kn) && m2 < 8) {
                        float den = dc - dn;
                        if (fabsf(den) < 1e-12f) den = 1e-12f;
                        float tt = dc / den;
                        swx[m2][t] = curx[ii] + tt * (qx - curx[ii]);
                        swy[m2][t] = cury[ii] + tt * (qy - cury[ii]);
                        m2++;
                    }
                }
            }
            n = m2;
            if (n == 0) break;
#pragma unroll
            for (int ii = 0; ii < 8; ii++) { curx[ii] = swx[ii][t]; cury[ii] = swy[ii][t]; }
        }
        float ia = 0.0f;
        if (n >= 3) {
            float s = 0.0f;
#pragma unroll
            for (int ii = 0; ii < 8; ii++) {
                if (ii < n) {
                    bool nlast = (ii + 1 < n);
                    float nx = nlast ? curx[ii + 1] : curx[0];
                    float ny = nlast ? cury[ii + 1] : cury[0];
                    s += curx[ii] * ny - nx * cury[ii];
                }
            }
            ia = 0.5f * fabsf(s);
        }
        float iou = ia / (oa + g_misc[g].x - ia + 1e-6f);

        unsigned bits = __float_as_uint(iou);
        atomicMax(&sab[a],
                  ((unsigned long long)bits << 32) |
                  (unsigned long long)(0xFFFFFFFFu - (unsigned)g));
        int oi = blockIdx.x * APB + a;
        atomicMax(&sbest[g],
                  ((unsigned long long)bits << 32) |
                  (unsigned long long)(0xFFFFFFFFu - (unsigned)oi));
    }

    __syncthreads();
    if (t < NG && sbest[t] != 0ULL)
        atomicMax(&d_gtbest[b * NG + t], sbest[t]);

    // -------- grid barrier (512 blocks co-resident) --------
    __syncthreads();
    if (t == 0) {
        __threadfence();
        atomicAdd((int*)&d_bar1, 1);
        while (d_bar1 < TOTBLK) __nanosleep(64);
        __threadfence();
    }
    __syncthreads();

    // -------- forced flags (s_isforced zeroed during setup, pre-barrier) --------
    if (t < NG) {
        unsigned long long gk = d_gtbest[b * NG + t];
        float mx = __uint_as_float((unsigned)(gk >> 32));
        int fa = (int)(0xFFFFFFFFu - (unsigned)(gk & 0xFFFFFFFFull));
        if (mx < 0.5f) {
            int rel = fa - blockIdx.x * APB;
            if (rel >= 0 && rel < APB) s_isforced[rel] = 1;
        }
    }
    __syncthreads();

    // -------- loss phase --------
    unsigned long long pk = sab[ai];
    float im = __uint_as_float((unsigned)(pk >> 32));
    int arg = (int)(0xFFFFFFFFu - (unsigned)(pk & 0xFFFFFFFFull));
    int p = (im >= 0.5f) || (s_isforced[ai] != 0);

    const float* cr = cls + ((size_t)b * NA + i) * NC;
    float csum = 0.0f;
    float rsum = 0.0f;

    if (p) {
        const float* gb = ann + ((size_t)b * NG + arg) * 6;
        int lab = (int)gb[5];
        if (h == 0) {
#pragma unroll
            for (int c_ = 0; c_ < 8; c_++) {
                float x = fminf(fmaxf(cr[c_], 1e-4f), 0.9999f);
                if (c_ == lab) {
                    float om = 1.0f - x;
                    csum += 0.25f * om * om * (-__logf(x + 1e-6f));
                } else {
                    csum += 0.75f * x * x * (-__logf(1.0f - x + 1e-6f));
                }
            }
            float gx0 = gb[0], gy0 = gb[1], gx1 = gb[2], gy1 = gb[3], gth = gb[4];
            float gcx = (gx0 + gx1) * 0.5f, gcy = (gy0 + gy1) * 0.5f;
            float gw = gx1 - gx0, gh2 = gy1 - gy0;
            float aw = s_aw[ai], ah = s_ah[ai], ath = s_ath[ai];
            float tgt5[5];
            tgt5[0] = (gcx - acx) / aw;
            tgt5[1] = (gcy - acy) / ah;
            tgt5[2] = logf(gw / aw);
            tgt5[3] = logf(gh2 / ah);
            tgt5[4] = (gth - ath) * (PI_F / 180.0f);
            const float* rr = reg + ((size_t)b * NA + i) * 5;
            const float beta = 1.0f / 9.0f;
#pragma unroll
            for (int k = 0; k < 5; k++) {
                float diff = fabsf(rr[k] - tgt5[k]);
                rsum += (diff < beta) ? (0.5f * diff * diff / beta) : (diff - 0.5f * beta);
            }
        } else {
#pragma unroll
            for (int c_ = 8; c_ < NC; c_++) {
                float x = fminf(fmaxf(cr[c_], 1e-4f), 0.9999f);
                if (c_ == lab) {
                    float om = 1.0f - x;
                    csum += 0.25f * om * om * (-__logf(x + 1e-6f));
                } else {
                    csum += 0.75f * x * x * (-__logf(1.0f - x + 1e-6f));
                }
            }
        }
    } else if (im < 0.4f) {
        if (h == 0) {
#pragma unroll
            for (int c_ = 0; c_ < 8; c_++) {
                float x = fminf(fmaxf(cr[c_], 1e-4f), 0.9999f);
                csum += 0.75f * x * x * (-__logf(1.0f - x + 1e-6f));
            }
        } else {
#pragma unroll
            for (int c_ = 8; c_ < NC; c_++) {
                float x = fminf(fmaxf(cr[c_], 1e-4f), 0.9999f);
                csum += 0.75f * x * x * (-__logf(1.0f - x + 1e-6f));
            }
        }
    }

    // warp reduce (double)
    double dc_ = (double)csum, dr_ = (double)rsum;
    int ip = (h == 0) ? p : 0;
#pragma unroll
    for (int off = 16; off > 0; off >>= 1) {
        dc_ += __shfl_down_sync(0xFFFFFFFFu, dc_, off);
        dr_ += __shfl_down_sync(0xFFFFFFFFu, dr_, off);
        ip  += __shfl_down_sync(0xFFFFFFFFu, ip, off);
    }
    if (lane == 0) { swc[w] = dc_; swr[w] = dr_; swp_[w] = ip; }
    __syncthreads();
    if (t == 0) {
        double tc = 0.0, tr = 0.0;
        int tp = 0;
#pragma unroll
        for (int k = 0; k < TPB / 32; k++) { tc += swc[k]; tr += swr[k]; tp += swp_[k]; }
        atomicAdd(&d_sum_cls[b], tc);
        atomicAdd(&d_sum_reg[b], tr);
        atomicAdd(&d_numpos[b], tp);
        __threadfence();
        int old = atomicAdd(&d_bar2, 1);
        if (old == TOTBLK - 1) {
            float lc = 0.0f, lr = 0.0f;
            for (int bb = 0; bb < B_; bb++) {
                int npv = d_numpos[bb];
                float npf = (float)(npv > 1 ? npv : 1);
                lc += (float)d_sum_cls[bb] / npf;
                lr += (npv > 0) ? ((float)d_sum_reg[bb] / (npf * 5.0f)) : 0.0f;
            }
            out[0] = 5.0f * (lc / (float)B_);
            out[1] = 2.0f * (lr / (float)B_);
            for (int bb = 0; bb < B_; bb++) {
                d_sum_cls[bb] = 0.0;
                d_sum_reg[bb] = 0.0;
                d_numpos[bb] = 0;
            }
            for (int k = 0; k < B_ * NG; k++) d_gtbest[k] = 0xFFFFFFFFull;
            d_bar1 = 0;
            __threadfence();
            d_bar2 = 0;
        }
    }
}

// ---------------- launch ----------------
extern "C" void kernel_launch(void* const* d_in, const int* in_sizes, int n_in,
                              void* d_out, int out_size) {
    const float* cls     = (const float*)d_in[0];
    const float* reg     = (const float*)d_in[1];
    const float* anchors = (const float*)d_in[2];
    const float* ann     = (const float*)d_in[3];
    float* out = (float*)d_out;

    dim3 grid(NBLKX, B_);
    kFused<<<grid, TPB>>>(cls, reg, anchors, ann, out);
}